// round 1
// baseline (speedup 1.0000x reference)
#include <cuda_runtime.h>
#include <cuda_bf16.h>

// Problem constants (match reference_code)
#define NPTS 8192
#define F0   8191      // N - 1 finite dim-0 pairs
#define E0   1
#define F1   4096
#define E1   8

// Output layout (flat fp32):
//   [0,            16382)  finite_dgm0  : rows (0, death)
//   [16382,        16383)  essential_dgm0 : 0
//   [16383,        24575)  finite_dgm1  : 2*F1 gathered distances
//   [24575,        24583)  essential_dgm1 : E1 gathered distances
#define OFF_E0  (2 * F0)            // 16382
#define OFF_F1  (OFF_E0 + E0)       // 16383
#define OFF_E1  (OFF_F1 + 2 * F1)   // 24575
#define TOTAL   (OFF_E1 + E1)       // 24583

__device__ __forceinline__ float pair_dist(const float* __restrict__ X, int a, int b) {
    // X is [N,3] row-major; rows are 12B. Use scalar __ldg; all hits L2/L1.
    float ax = __ldg(X + 3 * a + 0);
    float ay = __ldg(X + 3 * a + 1);
    float az = __ldg(X + 3 * a + 2);
    float bx = __ldg(X + 3 * b + 0);
    float by = __ldg(X + 3 * b + 1);
    float bz = __ldg(X + 3 * b + 2);
    float dx = ax - bx, dy = ay - by, dz = az - bz;
    return sqrtf(fmaf(dx, dx, fmaf(dy, dy, dz * dz)));
}

__global__ void rips_kernel(const float* __restrict__ X,
                            const int* __restrict__ idx0_finite,    // [F0,3]
                            const int* __restrict__ idx1_finite,    // [F1,4] == flat pairs [2*F1,2]
                            const int* __restrict__ idx1_essential, // [E1,2]
                            float* __restrict__ out) {
    int tid = blockIdx.x * blockDim.x + threadIdx.x;
    if (tid >= TOTAL) return;

    float v;
    if (tid < OFF_E0) {
        // finite_dgm0: even col = birth (0), odd col = death = DX[idx0f[r,1], idx0f[r,2]]
        if ((tid & 1) == 0) {
            v = 0.0f;
        } else {
            int r = tid >> 1;
            int a = __ldg(idx0_finite + 3 * r + 1);
            int b = __ldg(idx0_finite + 3 * r + 2);
            v = pair_dist(X, a, b);
        }
    } else if (tid < OFF_F1) {
        v = 0.0f;  // essential_dgm0
    } else if (tid < OFF_E1) {
        int j = tid - OFF_F1;          // flat pair index in [0, 2*F1)
        int a = __ldg(idx1_finite + 2 * j + 0);
        int b = __ldg(idx1_finite + 2 * j + 1);
        v = pair_dist(X, a, b);
    } else {
        int k = tid - OFF_E1;
        int a = __ldg(idx1_essential + 2 * k + 0);
        int b = __ldg(idx1_essential + 2 * k + 1);
        v = pair_dist(X, a, b);
    }
    out[tid] = v;
}

extern "C" void kernel_launch(void* const* d_in, const int* in_sizes, int n_in,
                              void* d_out, int out_size) {
    const float* X              = (const float*)d_in[0];
    const int*   idx0_finite    = (const int*)d_in[1];
    // d_in[2] = idx0_essential (unused; output is just zeros there)
    const int*   idx1_finite    = (const int*)d_in[3];
    const int*   idx1_essential = (const int*)d_in[4];
    float* out = (float*)d_out;

    const int threads = 256;
    const int blocks = (TOTAL + threads - 1) / threads;  // 97
    rips_kernel<<<blocks, threads>>>(X, idx0_finite, idx1_finite, idx1_essential, out);
}